// round 12
// baseline (speedup 1.0000x reference)
#include <cuda_runtime.h>
#include <cstdint>

__device__ __forceinline__ float cround1(float x) {
    uint32_t xb = __float_as_uint(x);
    float ns = __uint_as_float(((xb & 0x80000000u) ^ 0x80000000u) | 0x34000000u);
    return floorf((x + ns) + 0.5f);  // op-identical to reference custom_round
}

struct CosetR {
    float d;     // squared distance incl. flip correction
    float step;
    int   kk;    // 8 = no flip
};

__device__ __forceinline__ CosetR coset_eval(const float xv[8], float f[8]) {
    float e[8];
#pragma unroll
    for (int i = 0; i < 8; i++) {
        float xi = xv[i];
        uint32_t xb = __float_as_uint(xi);
        float sp = __uint_as_float(((xb & 0x80000000u) ^ 0x80000000u) | 0x34000000u);
        f[i] = floorf((xi + sp) + 0.5f);
        e[i] = xi - f[i];                 // exact
    }
    float fsum = ((f[0] + f[1]) + (f[2] + f[3])) + ((f[4] + f[5]) + (f[6] + f[7]));
    // parity from low mantissa bit of (fsum + 1.5*2^23): exact for |fsum| < 2^22
    int odd = (int)(__float_as_uint(fsum + 12582912.0f) & 1u);

    float d = 0.f;
#pragma unroll
    for (int i = 0; i < 8; i++) d = fmaf(e[i], e[i], d);

    // Tournament argmax of |e|, leftmost wins ties (== jnp.argmax).
    bool c01 = fabsf(e[1]) > fabsf(e[0]);
    float b01 = c01 ? e[1] : e[0];  int k01 = c01 ? 1 : 0;
    bool c23 = fabsf(e[3]) > fabsf(e[2]);
    float b23 = c23 ? e[3] : e[2];  int k23 = c23 ? 3 : 2;
    bool c45 = fabsf(e[5]) > fabsf(e[4]);
    float b45 = c45 ? e[5] : e[4];  int k45 = c45 ? 5 : 4;
    bool c67 = fabsf(e[7]) > fabsf(e[6]);
    float b67 = c67 ? e[7] : e[6];  int k67 = c67 ? 7 : 6;
    bool ca = fabsf(b23) > fabsf(b01);
    float ba = ca ? b23 : b01;      int ka = ca ? k23 : k01;
    bool cb = fabsf(b67) > fabsf(b45);
    float bb = cb ? b67 : b45;      int kb = cb ? k67 : k45;
    bool cf = fabsf(bb) > fabsf(ba);
    float be = cf ? bb : ba;        int k  = cf ? kb : ka;

    // step: sign(be); be==0 => all e==0 => k==0, x0==f0 => -sign(f0).
    float sgn   = __uint_as_float((__float_as_uint(be)   & 0x80000000u) | 0x3f800000u);
    float zstep = __uint_as_float(((__float_as_uint(f[0]) & 0x80000000u) ^ 0x80000000u) | 0x3f800000u);
    float step = (be == 0.f) ? zstep : sgn;

    // flipped distance = d + 1 - 2|be| (exact correction; step = sgn(be) if be!=0)
    float adj = fmaf(-2.f, fabsf(be), 1.f);

    CosetR r;
    r.kk   = odd ? k : 8;
    r.d    = odd ? (d + adj) : d;
    r.step = step;
    return r;
}

// E8 = D8 U (D8 + 1/2); ties (d0==d1) pick coset 1, matching reference.
__device__ __forceinline__ void closest_E8(const float x[8], float y[8]) {
    float f0[8], f1[8], xs[8];
    CosetR c0 = coset_eval(x, f0);
#pragma unroll
    for (int i = 0; i < 8; i++) xs[i] = x[i] - 0.5f;
    CosetR c1 = coset_eval(xs, f1);

    bool pick0 = c0.d < c1.d;
    int   kk = pick0 ? c0.kk : c1.kk;
    float st = pick0 ? c0.step : c1.step;
    float hb = pick0 ? 0.f : 0.5f;
#pragma unroll
    for (int i = 0; i < 8; i++) {
        float yi = (pick0 ? f0[i] : f1[i]) + hb;
        if (i == kk) yi += st;
        y[i] = yi;
    }
}

__global__ __launch_bounds__(256, 4)
void LatticeQuantizer_kernel(const float* __restrict__ x,
                             const float* __restrict__ betap,
                             const float* __restrict__ epsp,
                             float* __restrict__ out, int N) {
    int r = blockIdx.x * blockDim.x + threadIdx.x;
    if (r >= N) return;

    const float4* x4 = reinterpret_cast<const float4*>(x);
    float4 a  = x4[2 * r];
    float4 bv = x4[2 * r + 1];

    float beta = __ldg(betap);
    bool b1 = (beta == 1.0f);                    // deterministic per-input
    float ib = b1 ? 1.0f : (1.0f / beta);

    float4 e0 = __ldg(reinterpret_cast<const float4*>(epsp));
    float4 e1 = __ldg(reinterpret_cast<const float4*>(epsp) + 1);
    float ep[8] = {e0.x, e0.y, e0.z, e0.w, e1.x, e1.y, e1.z, e1.w};

    float xin[8] = {a.x, a.y, a.z, a.w, bv.x, bv.y, bv.z, bv.w};
    float cur[8];
#pragma unroll
    for (int i = 0; i < 8; i++)
        cur[i] = b1 ? (xin[i] + ep[i]) : (xin[i] * ib + ep[i]);

    float xh[8] = {0.f, 0.f, 0.f, 0.f, 0.f, 0.f, 0.f, 0.f};
    float scale = 1.f;

    // Rolled layer loop (inner loops stay unrolled): small body, low regs.
#pragma unroll 1
    for (int m = 0; m < 3; m++) {
        // ---------------- encode layer m ----------------
        float cp[8];
        closest_E8(cur, cp);

        // z = cp @ G_inv via exact forward solve (rows * z = cp);
        // z is quarter-integer on the half coset -> cround after fmod REQUIRED.
        float z[8];
        z[0] = 0.5f * cp[0];
#pragma unroll
        for (int i = 1; i < 7; i++) z[i] = cp[i] + z[i - 1];
        float s06 = ((z[0] + z[1]) + (z[2] + z[3])) + ((z[4] + z[5]) + z[6]);
        z[7] = fmaf(2.f, cp[7], -s06);

        float b[8];
#pragma unroll
        for (int i = 0; i < 8; i++) {
            float q = truncf(z[i] * 0.25f);        // exact (1/16 grid)
            float mres = fmaf(-4.f, q, z[i]);      // exact quarter-int in (-4,4)
            b[i] = cround1(mres);                  // MUST be op-identical cround
        }

        // next-layer input (dead compute on last iter; keeps loop branchless)
#pragma unroll
        for (int i = 0; i < 8; i++)
            cur[i] = fmaf(cp[i], 0.25f, ep[i]);    // cp*0.25 exact

        // ---------------- decode layer m (fused) ----------------
        float Gb[8];
        Gb[0] = fmaf(0.5f, b[7], fmaf(2.f, b[0], -b[1]));
#pragma unroll
        for (int j = 1; j < 6; j++) Gb[j] = fmaf(0.5f, b[7], b[j] - b[j + 1]);
        Gb[6] = fmaf(0.5f, b[7], b[6]);
        Gb[7] = 0.5f * b[7];

        float gq[8], cq[8];
#pragma unroll
        for (int i = 0; i < 8; i++) gq[i] = Gb[i] * 0.25f;   // exact (1/8 grid)
        closest_E8(gq, cq);

#pragma unroll
        for (int i = 0; i < 8; i++) {
            float xi = fmaf(-4.f, cq[i], Gb[i]);             // exact
            xh[i] = fmaf(scale, xi, xh[i]);                  // exact dyadic (scale = 4^m)
        }
        scale *= 4.f;                                        // exact
    }

    float4 o0, o1;
    if (b1) {
        o0.x = xh[0]; o0.y = xh[1]; o0.z = xh[2]; o0.w = xh[3];
        o1.x = xh[4]; o1.y = xh[5]; o1.z = xh[6]; o1.w = xh[7];
    } else {
        o0.x = beta * xh[0]; o0.y = beta * xh[1];
        o0.z = beta * xh[2]; o0.w = beta * xh[3];
        o1.x = beta * xh[4]; o1.y = beta * xh[5];
        o1.z = beta * xh[6]; o1.w = beta * xh[7];
    }
    float4* out4 = reinterpret_cast<float4*>(out);
    out4[2 * r]     = o0;
    out4[2 * r + 1] = o1;
}

extern "C" void kernel_launch(void* const* d_in, const int* in_sizes, int n_in,
                              void* d_out, int out_size) {
    const float* x    = (const float*)d_in[0];
    const float* beta = (const float*)d_in[1];
    const float* eps  = (const float*)d_in[4];
    float* out = (float*)d_out;

    int N = in_sizes[0] / 8;
    int threads = 256;
    int blocks = (N + threads - 1) / threads;
    LatticeQuantizer_kernel<<<blocks, threads>>>(x, beta, eps, out, N);
}

// round 13
// speedup vs baseline: 1.0356x; 1.0356x over previous
#include <cuda_runtime.h>
#include <cstdint>

__device__ __forceinline__ float cround1(float x) {
    uint32_t xb = __float_as_uint(x);
    float ns = __uint_as_float(((xb & 0x80000000u) ^ 0x80000000u) | 0x34000000u);
    return floorf((x + ns) + 0.5f);  // op-identical to reference custom_round
}

struct CosetR {
    float d;
    float step;
    int   kk;    // 8 = no flip
};

__device__ __forceinline__ CosetR coset_eval(const float xv[8], float f[8]) {
    float e[8];
#pragma unroll
    for (int i = 0; i < 8; i++) {
        float xi = xv[i];
        uint32_t xb = __float_as_uint(xi);
        float sp = __uint_as_float(((xb & 0x80000000u) ^ 0x80000000u) | 0x34000000u);
        f[i] = floorf((xi + sp) + 0.5f);
        e[i] = xi - f[i];                 // exact
    }
    float fsum = ((f[0] + f[1]) + (f[2] + f[3])) + ((f[4] + f[5]) + (f[6] + f[7]));
    int odd = (int)(__float_as_uint(fsum + 12582912.0f) & 1u);  // exact parity

    float d = 0.f;
#pragma unroll
    for (int i = 0; i < 8; i++) d = fmaf(e[i], e[i], d);

    // Tournament argmax of |e|, leftmost wins ties (== jnp.argmax).
    bool c01 = fabsf(e[1]) > fabsf(e[0]);
    float b01 = c01 ? e[1] : e[0];  int k01 = c01 ? 1 : 0;
    bool c23 = fabsf(e[3]) > fabsf(e[2]);
    float b23 = c23 ? e[3] : e[2];  int k23 = c23 ? 3 : 2;
    bool c45 = fabsf(e[5]) > fabsf(e[4]);
    float b45 = c45 ? e[5] : e[4];  int k45 = c45 ? 5 : 4;
    bool c67 = fabsf(e[7]) > fabsf(e[6]);
    float b67 = c67 ? e[7] : e[6];  int k67 = c67 ? 7 : 6;
    bool ca = fabsf(b23) > fabsf(b01);
    float ba = ca ? b23 : b01;      int ka = ca ? k23 : k01;
    bool cb = fabsf(b67) > fabsf(b45);
    float bb = cb ? b67 : b45;      int kb = cb ? k67 : k45;
    bool cf = fabsf(bb) > fabsf(ba);
    float be = cf ? bb : ba;        int k  = cf ? kb : ka;

    float sgn   = __uint_as_float((__float_as_uint(be)   & 0x80000000u) | 0x3f800000u);
    float zstep = __uint_as_float(((__float_as_uint(f[0]) & 0x80000000u) ^ 0x80000000u) | 0x3f800000u);
    float step = (be == 0.f) ? zstep : sgn;

    float adj = fmaf(-2.f, fabsf(be), 1.f);   // flipped d = d + 1 - 2|be|

    CosetR r;
    r.kk   = odd ? k : 8;
    r.d    = odd ? (d + adj) : d;
    r.step = step;
    return r;
}

__device__ __forceinline__ void closest_E8(const float x[8], float y[8]) {
    float f0[8], f1[8], xs[8];
    CosetR c0 = coset_eval(x, f0);
#pragma unroll
    for (int i = 0; i < 8; i++) xs[i] = x[i] - 0.5f;
    CosetR c1 = coset_eval(xs, f1);

    bool pick0 = c0.d < c1.d;                 // ties -> coset 1, as reference
    int   kk = pick0 ? c0.kk : c1.kk;
    float st = pick0 ? c0.step : c1.step;
    float hb = pick0 ? 0.f : 0.5f;
#pragma unroll
    for (int i = 0; i < 8; i++) {
        float yi = (pick0 ? f0[i] : f1[i]) + hb;
        if (i == kk) yi += st;
        y[i] = yi;
    }
}

// One layer of encode+decode for one row. cur -> updated in place; xh accumulated.
__device__ __forceinline__ void layer_step(float cur[8], float xh[8],
                                           const float ep[8], float scale) {
    float cp[8];
    closest_E8(cur, cp);

    // z = cp @ G_inv (exact forward solve); quarter-int on half coset ->
    // cround after fmod REQUIRED.
    float z[8];
    z[0] = 0.5f * cp[0];
#pragma unroll
    for (int i = 1; i < 7; i++) z[i] = cp[i] + z[i - 1];
    float s06 = ((z[0] + z[1]) + (z[2] + z[3])) + ((z[4] + z[5]) + z[6]);
    z[7] = fmaf(2.f, cp[7], -s06);

    float b[8];
#pragma unroll
    for (int i = 0; i < 8; i++) {
        float q = truncf(z[i] * 0.25f);
        float mres = fmaf(-4.f, q, z[i]);
        b[i] = cround1(mres);
    }

#pragma unroll
    for (int i = 0; i < 8; i++)
        cur[i] = fmaf(cp[i], 0.25f, ep[i]);   // next layer input (exact)

    float Gb[8];
    Gb[0] = fmaf(0.5f, b[7], fmaf(2.f, b[0], -b[1]));
#pragma unroll
    for (int j = 1; j < 6; j++) Gb[j] = fmaf(0.5f, b[7], b[j] - b[j + 1]);
    Gb[6] = fmaf(0.5f, b[7], b[6]);
    Gb[7] = 0.5f * b[7];

    float gq[8], cq[8];
#pragma unroll
    for (int i = 0; i < 8; i++) gq[i] = Gb[i] * 0.25f;
    closest_E8(gq, cq);

#pragma unroll
    for (int i = 0; i < 8; i++) {
        float xi = fmaf(-4.f, cq[i], Gb[i]);
        xh[i] = fmaf(scale, xi, xh[i]);
    }
}

__global__ __launch_bounds__(256, 2)
void LatticeQuantizer_kernel(const float* __restrict__ x,
                             const float* __restrict__ betap,
                             const float* __restrict__ epsp,
                             float* __restrict__ out, int N) {
    int t = blockIdx.x * blockDim.x + threadIdx.x;
    int half = N >> 1;                       // N = 4194304, even
    if (t >= half) return;
    int rA = t;                              // both streams coalesced
    int rB = t + half;

    const float4* x4 = reinterpret_cast<const float4*>(x);
    float4 a0 = x4[2 * rA], a1 = x4[2 * rA + 1];
    float4 b0 = x4[2 * rB], b1v = x4[2 * rB + 1];

    float beta = __ldg(betap);
    bool bOne = (beta == 1.0f);
    float ib = bOne ? 1.0f : (1.0f / beta);

    float4 e0 = __ldg(reinterpret_cast<const float4*>(epsp));
    float4 e1 = __ldg(reinterpret_cast<const float4*>(epsp) + 1);
    float ep[8] = {e0.x, e0.y, e0.z, e0.w, e1.x, e1.y, e1.z, e1.w};

    float inA[8] = {a0.x, a0.y, a0.z, a0.w, a1.x, a1.y, a1.z, a1.w};
    float inB[8] = {b0.x, b0.y, b0.z, b0.w, b1v.x, b1v.y, b1v.z, b1v.w};

    float curA[8], curB[8], xhA[8], xhB[8];
#pragma unroll
    for (int i = 0; i < 8; i++) {
        curA[i] = bOne ? (inA[i] + ep[i]) : (inA[i] * ib + ep[i]);
        curB[i] = bOne ? (inB[i] + ep[i]) : (inB[i] * ib + ep[i]);
        xhA[i] = 0.f;
        xhB[i] = 0.f;
    }

    float scale = 1.f;
#pragma unroll 1
    for (int m = 0; m < 3; m++) {
        // Two independent rows per iteration -> 2x ILP for the scheduler.
        layer_step(curA, xhA, ep, scale);
        layer_step(curB, xhB, ep, scale);
        scale *= 4.f;
    }

    float4 oA0, oA1, oB0, oB1;
    if (bOne) {
        oA0 = make_float4(xhA[0], xhA[1], xhA[2], xhA[3]);
        oA1 = make_float4(xhA[4], xhA[5], xhA[6], xhA[7]);
        oB0 = make_float4(xhB[0], xhB[1], xhB[2], xhB[3]);
        oB1 = make_float4(xhB[4], xhB[5], xhB[6], xhB[7]);
    } else {
        oA0 = make_float4(beta * xhA[0], beta * xhA[1], beta * xhA[2], beta * xhA[3]);
        oA1 = make_float4(beta * xhA[4], beta * xhA[5], beta * xhA[6], beta * xhA[7]);
        oB0 = make_float4(beta * xhB[0], beta * xhB[1], beta * xhB[2], beta * xhB[3]);
        oB1 = make_float4(beta * xhB[4], beta * xhB[5], beta * xhB[6], beta * xhB[7]);
    }
    float4* out4 = reinterpret_cast<float4*>(out);
    out4[2 * rA]     = oA0;
    out4[2 * rA + 1] = oA1;
    out4[2 * rB]     = oB0;
    out4[2 * rB + 1] = oB1;
}

extern "C" void kernel_launch(void* const* d_in, const int* in_sizes, int n_in,
                              void* d_out, int out_size) {
    const float* x    = (const float*)d_in[0];
    const float* beta = (const float*)d_in[1];
    const float* eps  = (const float*)d_in[4];
    float* out = (float*)d_out;

    int N = in_sizes[0] / 8;
    int half = N / 2;
    int threads = 256;
    int blocks = (half + threads - 1) / threads;
    LatticeQuantizer_kernel<<<blocks, threads>>>(x, beta, eps, out, N);
}